// round 15
// baseline (speedup 1.0000x reference)
#include <cuda_runtime.h>

#define Bv 8
#define Nv 256
#define Dv 128
#define Ev 32
#define Hv 4
#define HDv 32
#define BN (Bv*Nv)

// ---------------- scratch (device globals; no allocation allowed) ----------------
__device__ float g_wke[Dv*Ev];
__device__ float g_wve[Dv*Ev];
__device__ float g_q  [BN*Dv];
__device__ float g_kh [BN*Dv];
__device__ float g_vh [BN*Dv];
__device__ float g_S0 [Bv*Hv*Nv*Nv];    // [b][h][n][m]
__device__ float g_hagg[BN*Dv];

// ---------------- K0: fused front: proj (blk<256) | gcn (256..511) | prep (512..543) ----
__global__ __launch_bounds__(384) void k_front(const float* __restrict__ hin,
                                               const float* __restrict__ adj,
                                               const float* __restrict__ wq,
                                               const float* __restrict__ wk,
                                               const float* __restrict__ wv,
                                               const float* __restrict__ bq,
                                               const float* __restrict__ bk,
                                               const float* __restrict__ bv,
                                               const float* __restrict__ edge_w,
                                               const float* __restrict__ edge_b) {
    int blk = blockIdx.x, t = threadIdx.x;
    if (blk < 256) {
        __shared__ float hs[9*Dv];
        int bn0 = blk << 3;
        for (int i = t; i < 9*Dv; i += 384)
            hs[i] = (i < 8*Dv) ? hin[(size_t)bn0*Dv + i] : edge_b[i - 8*Dv];
        __syncthreads();
        int mat = t >> 7, d = t & 127;
        const float* W = (mat == 0) ? wq : (mat == 1) ? wk : wv;
        float bias = (mat == 0) ? bq[d] : (mat == 1) ? bk[d] : bv[d];
        float acc[9];
        #pragma unroll
        for (int r = 0; r < 9; r++) acc[r] = 0.f;
        const float4* W4 = (const float4*)W;
        const float4* hs4 = (const float4*)hs;
        #pragma unroll 4
        for (int j4 = 0; j4 < 32; j4++) {
            float4 w = W4[d*32 + j4];
            #pragma unroll
            for (int r = 0; r < 9; r++) {
                float4 hv = hs4[r*32 + j4];
                acc[r] += w.x*hv.x + w.y*hv.y + w.z*hv.z + w.w*hv.w;
            }
        }
        float* dst = (mat == 0) ? g_q : (mat == 1) ? g_kh : g_vh;
        float cadd = (mat == 0) ? bias : (bias + acc[8]);
        #pragma unroll
        for (int r = 0; r < 8; r++)
            dst[(size_t)(bn0 + r)*Dv + d] = acc[r] + cadd;
    } else if (blk < 512) {
        __shared__ float adjs[8*Nv];
        __shared__ float part[3*8*Dv];
        __shared__ float degs[8];
        int g = blk - 256; int b = g >> 5; int n0 = (g & 31) << 3;
        for (int i = t; i < 8*Nv; i += 384) {
            int r = i >> 8, m = i & 255;
            adjs[i] = adj[((size_t)b*Nv + (n0+r))*Nv + m];
        }
        __syncthreads();
        if (t < 8) adjs[t*Nv + n0 + t] += 1.0f;
        __syncthreads();
        if (t < 128) {
            int r = t >> 4, lane = t & 15;
            float p = 0.f;
            #pragma unroll
            for (int k = 0; k < 16; k++) p += adjs[r*Nv + lane*16 + k];
            #pragma unroll
            for (int o = 8; o > 0; o >>= 1) p += __shfl_xor_sync(0xffffffffu, p, o, 16);
            if (lane == 0) degs[r] = p;
        }
        __syncthreads();
        int grp = t >> 7, d = t & 127;
        const int mlo = (grp == 0) ? 0 : (grp == 1) ? 86 : 171;
        const int mhi = (grp == 0) ? 86 : (grp == 1) ? 171 : 256;
        float acc[8];
        #pragma unroll
        for (int r = 0; r < 8; r++) acc[r] = 0.f;
        for (int m = mlo; m < mhi; m++) {
            float hv = hin[((size_t)b*Nv + m)*Dv + d];
            #pragma unroll
            for (int r = 0; r < 8; r++) acc[r] += adjs[r*Nv + m] * hv;
        }
        #pragma unroll
        for (int r = 0; r < 8; r++) part[grp*8*Dv + r*Dv + d] = acc[r];
        __syncthreads();
        if (t < 128) {
            #pragma unroll
            for (int r = 0; r < 8; r++) {
                float s = part[0*8*Dv + r*Dv + t] + part[1*8*Dv + r*Dv + t] + part[2*8*Dv + r*Dv + t];
                g_hagg[((size_t)b*Nv + n0 + r)*Dv + t] = s / degs[r];
            }
        }
    } else {
        if (t < 128) {
            int pb = blk - 512;
            int dl = t >> 5, e = t & 31;
            int d = pb * 4 + dl;
            float sk = 0.f, sv = 0.f;
            #pragma unroll 8
            for (int j = 0; j < Dv; j++) {
                float ew = edge_w[j*Ev + e];
                sk += wk[d*Dv + j] * ew;
                sv += wv[d*Dv + j] * ew;
            }
            g_wke[d*Ev + e] = sk;
            g_wve[d*Ev + e] = sv;
        }
    }
}

// ---------------- K1: S0 = Q_h K_h^T (32x64 tiles, grid 1024) ----------------
__global__ __launch_bounds__(256) void k_s0() {
    int bh = blockIdx.x; int b = bh >> 2, h = bh & 3;
    int n0 = blockIdx.y << 5, m0 = blockIdx.z << 6;
    __shared__ float Qt[32*33];
    __shared__ float Kt[64*33];
    int t = threadIdx.x;
    {
        int r = t >> 3, c4 = (t & 7) << 2;
        float4 w0 = *(const float4*)(g_kh + ((size_t)(b*Nv + m0 + r))*Dv + h*HDv + c4);
        float* q0 = &Kt[r*33 + c4];
        q0[0]=w0.x; q0[1]=w0.y; q0[2]=w0.z; q0[3]=w0.w;
        float4 w1 = *(const float4*)(g_kh + ((size_t)(b*Nv + m0 + 32 + r))*Dv + h*HDv + c4);
        float* q1 = &Kt[(32+r)*33 + c4];
        q1[0]=w1.x; q1[1]=w1.y; q1[2]=w1.z; q1[3]=w1.w;
        if (r < 32) {
            float4 v = *(const float4*)(g_q + ((size_t)(b*Nv + n0 + r))*Dv + h*HDv + c4);
            float* p = &Qt[r*33 + c4];
            p[0]=v.x; p[1]=v.y; p[2]=v.z; p[3]=v.w;
        }
    }
    __syncthreads();
    int tx = t & 15, ty = t >> 4;
    float acc[2][4];
    #pragma unroll
    for (int i = 0; i < 2; i++)
        #pragma unroll
        for (int j = 0; j < 4; j++) acc[i][j] = 0.f;
    #pragma unroll 4
    for (int e = 0; e < HDv; e++) {
        float qr[2], kr[4];
        qr[0] = Qt[(ty*2+0)*33 + e];
        qr[1] = Qt[(ty*2+1)*33 + e];
        #pragma unroll
        for (int j = 0; j < 4; j++) kr[j] = Kt[(tx*4+j)*33 + e];
        #pragma unroll
        for (int i = 0; i < 2; i++)
            #pragma unroll
            for (int j = 0; j < 4; j++) acc[i][j] += qr[i]*kr[j];
    }
    float* dst = g_S0 + (size_t)(b*Hv + h)*Nv*Nv;
    #pragma unroll
    for (int i = 0; i < 2; i++) {
        float* p = dst + (size_t)(n0 + ty*2 + i)*Nv + m0 + tx*4;
        *(float4*)p = make_float4(acc[i][0],acc[i][1],acc[i][2],acc[i][3]);
    }
}

// ------- K2: FUSED attention + out-proj + gcn-proj + LN (one CTA = 8 rows) --------
// Attention phase identical to R14 k_att2; tail replaces g_o1 write with in-smem
// os[] and runs the former k_final for the same 8 rows.
__global__ __launch_bounds__(256) void k_att3(const float* __restrict__ ef,
                                              const float* __restrict__ adj,
                                              const float* __restrict__ srcm,
                                              const float* __restrict__ hin,
                                              const float* __restrict__ out_w,
                                              const float* __restrict__ out_b,
                                              const float* __restrict__ gcn_w,
                                              const float* __restrict__ gcn_b,
                                              const float* __restrict__ ln_g,
                                              const float* __restrict__ ln_b,
                                              float* __restrict__ out) {
    int blk = blockIdx.x; int b = blk >> 5; int n0 = (blk & 31) << 3;
    __shared__ float sm[11520];            // 46080 B
    float* s_qrow = sm;                    // [8][128]  (later: aes; then hs)
    float* s_qks  = sm + 1024;             // [8][128]  (later: hag)
    float* s_efs  = sm + 2048;             // [8][32][33] pitch-33 (later: wvet; then yb/gb)
    float* s_exch = sm + 10496;            // [8][32] float4 (exp per head)
    float* s_os   = sm + 6144;             // [8][128] attention output (free zone during o2)

    int t = threadIdx.x;
    int n = t >> 5;                        // warp = n-row
    int x = t & 31;                        // lane
    int bn = b*Nv + n0 + n;

    *(float4*)&s_qrow[t*4] = *(const float4*)(g_q + ((size_t)(b*Nv + n0))*Dv + t*4);
    __syncwarp();
    #pragma unroll
    for (int h = 0; h < 4; h++) {
        float s = 0.f;
        #pragma unroll 8
        for (int j = 0; j < 32; j++)
            s += s_qrow[n*128 + h*32 + j] * g_wke[(h*32 + j)*Ev + x];
        s_qks[n*128 + h*32 + x] = s;
    }
    __syncwarp();

    const float SCALE = 0.17677669529663687f;   // 1/sqrt(32)
    float4 o1a = make_float4(0.f,0.f,0.f,0.f);
    float4 den4 = make_float4(0.f,0.f,0.f,0.f);
    float ae0=0.f, ae1=0.f, ae2=0.f, ae3=0.f;
    int ho = x >> 3;

    for (int mc = 0; mc < Nv; mc += 32) {
        int m = mc + x;
        {
            const float4* src = (const float4*)(ef + ((size_t)bn*Nv + mc)*Ev);
            float* dst = s_efs + n*1056;
            #pragma unroll
            for (int it = 0; it < 8; it++) {
                int idx = it*32 + x;
                int row = idx >> 3, e4 = idx & 7;
                float4 v = src[idx];
                float* p = &dst[row*33 + (e4 << 2)];
                p[0]=v.x; p[1]=v.y; p[2]=v.z; p[3]=v.w;
            }
        }
        float wmask = adj[(size_t)bn*Nv + m] * srcm[(size_t)bn*Nv + m];
        float s00 = g_S0[((size_t)(b*Hv+0)*Nv + (n0+n))*Nv + m];
        float s01 = g_S0[((size_t)(b*Hv+1)*Nv + (n0+n))*Nv + m];
        float s02 = g_S0[((size_t)(b*Hv+2)*Nv + (n0+n))*Nv + m];
        float s03 = g_S0[((size_t)(b*Hv+3)*Nv + (n0+n))*Nv + m];
        __syncwarp();
        float es0=0.f, es1=0.f, es2=0.f, es3=0.f;
        {
            const float* myrow = s_efs + n*1056 + x*33;
            #pragma unroll
            for (int e4 = 0; e4 < 8; e4++) {
                float f0 = myrow[e4*4+0], f1 = myrow[e4*4+1],
                      f2 = myrow[e4*4+2], f3 = myrow[e4*4+3];
                float4 q0 = *(const float4*)&s_qks[n*128 + 0*32 + e4*4];
                float4 q1 = *(const float4*)&s_qks[n*128 + 1*32 + e4*4];
                float4 q2 = *(const float4*)&s_qks[n*128 + 2*32 + e4*4];
                float4 q3 = *(const float4*)&s_qks[n*128 + 3*32 + e4*4];
                es0 += f0*q0.x + f1*q0.y + f2*q0.z + f3*q0.w;
                es1 += f0*q1.x + f1*q1.y + f2*q1.z + f3*q1.w;
                es2 += f0*q2.x + f1*q2.y + f2*q2.z + f3*q2.w;
                es3 += f0*q3.x + f1*q3.y + f2*q3.z + f3*q3.w;
            }
        }
        float4 exv;
        if (wmask == 0.0f) {
            exv = make_float4(0.f,0.f,0.f,0.f);
        } else {
            exv.x = __expf((s00+es0)*SCALE);
            exv.y = __expf((s01+es1)*SCALE);
            exv.z = __expf((s02+es2)*SCALE);
            exv.w = __expf((s03+es3)*SCALE);
        }
        *(float4*)&s_exch[t*4] = exv;
        {
            float4 cs = exv;
            #pragma unroll
            for (int o = 16; o > 0; o >>= 1) {
                cs.x += __shfl_xor_sync(0xffffffffu, cs.x, o);
                cs.y += __shfl_xor_sync(0xffffffffu, cs.y, o);
                cs.z += __shfl_xor_sync(0xffffffffu, cs.z, o);
                cs.w += __shfl_xor_sync(0xffffffffu, cs.w, o);
            }
            den4.x += cs.x; den4.y += cs.y; den4.z += cs.z; den4.w += cs.w;
        }
        __syncwarp();

        const float* vbase = g_vh + ((size_t)(b*Nv + mc))*Dv;
        #pragma unroll 4
        for (int mm = 0; mm < 32; mm++) {
            float exm = s_exch[(n*32+mm)*4 + ho];
            float4 vv = *(const float4*)(vbase + (size_t)mm*Dv + x*4);
            o1a.x += exm*vv.x; o1a.y += exm*vv.y; o1a.z += exm*vv.z; o1a.w += exm*vv.w;
        }
        {
            const float* wef = s_efs + n*1056;
            #pragma unroll 4
            for (int mm = 0; mm < 32; mm++) {
                float4 e4v = *(const float4*)&s_exch[(n*32+mm)*4];
                float fv = wef[mm*33 + x];
                ae0 += e4v.x*fv; ae1 += e4v.y*fv; ae2 += e4v.z*fv; ae3 += e4v.w*fv;
            }
        }
        __syncwarp();
    }

    // normalize ae -> aes (reuse s_qrow)
    {
        float* aes = s_qrow;
        aes[(n*4+0)*32 + x] = ae0 / den4.x;
        aes[(n*4+1)*32 + x] = ae1 / den4.y;
        aes[(n*4+2)*32 + x] = ae2 / den4.z;
        aes[(n*4+3)*32 + x] = ae3 / den4.w;
    }
    __syncthreads();
    // stage wve^T (32e x 128d) into s_efs (first 16 KB)
    #pragma unroll
    for (int i = 0; i < 16; i++) {
        int idx = i*256 + t;
        int e = idx >> 7, d = idx & 127;
        s_efs[e*128 + d] = g_wve[d*Ev + e];
    }
    __syncthreads();
    // o2 + write attention output into smem os (free zone, no overlap with aes/wvet)
    {
        float den1 = (ho == 0) ? den4.x : (ho == 1) ? den4.y : (ho == 2) ? den4.z : den4.w;
        float inv = 1.0f / den1;
        float4 res = make_float4(o1a.x*inv, o1a.y*inv, o1a.z*inv, o1a.w*inv);
        const float* aes = s_qrow + (n*4 + ho)*32;
        #pragma unroll 8
        for (int e = 0; e < 32; e++) {
            float a = aes[e];
            float4 wv = *(const float4*)&s_efs[e*128 + x*4];
            res.x += a*wv.x; res.y += a*wv.y; res.z += a*wv.z; res.w += a*wv.w;
        }
        *(float4*)&s_os[n*128 + x*4] = res;
    }
    __syncthreads();   // os complete; aes/wvet now dead -> overlay tail buffers

    // ---- fused former k_final: out-proj + gcn-proj + LN for these 8 rows ----
    float* s_hs  = sm;            // [8][128]
    float* s_hag = sm + 1024;     // [8][128]
    float* s_yb  = sm + 2048;     // [8][128]
    float* s_gb  = sm + 3072;     // [8][128]
    {
        size_t gi = (size_t)(b*Nv + n0)*Dv;
        // 256 threads load 1024 floats each array (4 per thread, coalesced float4)
        *(float4*)&s_hs [t*4] = *(const float4*)(hin   + gi + t*4);
        *(float4*)&s_hag[t*4] = *(const float4*)(g_hagg + gi + t*4);
    }
    __syncthreads();
    {
        int grp = t >> 7, d = t & 127;
        const float4* W4 = (const float4*)(grp ? gcn_w : out_w);
        const float4* X4 = (const float4*)(grp ? s_hag : s_os);
        float bias = grp ? gcn_b[d] : out_b[d];
        float* Y = grp ? s_gb : s_yb;
        float acc[8];
        #pragma unroll
        for (int r = 0; r < 8; r++) acc[r] = bias;
        #pragma unroll 4
        for (int j4 = 0; j4 < 32; j4++) {
            float4 w = W4[d*32 + j4];
            #pragma unroll
            for (int r = 0; r < 8; r++) {
                float4 hv = X4[r*32 + j4];
                acc[r] += w.x*hv.x + w.y*hv.y + w.z*hv.z + w.w*hv.w;
            }
        }
        #pragma unroll
        for (int r = 0; r < 8; r++) Y[r*Dv + d] = acc[r];
    }
    __syncthreads();
    {
        // warp n handles row n; lane x handles d = 4x..4x+3
        float4 a  = *(const float4*)&s_hs[n*128 + x*4];
        float4 yv = *(const float4*)&s_yb[n*128 + x*4];
        float x0 = a.x + yv.x, x1 = a.y + yv.y, x2 = a.z + yv.z, x3 = a.w + yv.w;
        float s = x0 + x1 + x2 + x3;
        #pragma unroll
        for (int o = 16; o > 0; o >>= 1) s += __shfl_xor_sync(0xffffffffu, s, o);
        float mu = s * (1.0f/128.0f);
        float c0 = x0-mu, c1 = x1-mu, c2 = x2-mu, c3 = x3-mu;
        float vv = c0*c0 + c1*c1 + c2*c2 + c3*c3;
        #pragma unroll
        for (int o = 16; o > 0; o >>= 1) vv += __shfl_xor_sync(0xffffffffu, vv, o);
        float rs = rsqrtf(vv * (1.0f/128.0f) + 1e-5f);
        float4 g  = ((const float4*)ln_g)[x];
        float4 lb = ((const float4*)ln_b)[x];
        float4 gg = *(const float4*)&s_gb[n*128 + x*4];
        float4 res;
        res.x = gg.x + g.x*c0*rs + lb.x;
        res.y = gg.y + g.y*c1*rs + lb.y;
        res.z = gg.z + g.z*c2*rs + lb.z;
        res.w = gg.w + g.w*c3*rs + lb.w;
        *(float4*)(out + (size_t)bn*Dv + x*4) = res;
    }
}

extern "C" void kernel_launch(void* const* d_in, const int* in_sizes, int n_in,
                              void* d_out, int out_size) {
    const float* h     = (const float*)d_in[0];
    const float* adj   = (const float*)d_in[1];
    const float* ef    = (const float*)d_in[2];
    const float* smk   = (const float*)d_in[3];
    const float* gcn_w = (const float*)d_in[4];
    const float* gcn_b = (const float*)d_in[5];
    const float* edge_w= (const float*)d_in[6];
    const float* edge_b= (const float*)d_in[7];
    const float* wq    = (const float*)d_in[8];
    const float* wk    = (const float*)d_in[9];
    const float* wv    = (const float*)d_in[10];
    const float* bq    = (const float*)d_in[11];
    const float* bk    = (const float*)d_in[12];
    const float* bv    = (const float*)d_in[13];
    const float* out_w = (const float*)d_in[14];
    const float* out_b = (const float*)d_in[15];
    const float* ln_g  = (const float*)d_in[16];
    const float* ln_b  = (const float*)d_in[17];
    float* out = (float*)d_out;

    k_front<<<544, 384>>>(h, adj, wq, wk, wv, bq, bk, bv, edge_w, edge_b);
    k_s0   <<<dim3(Bv*Hv, 8, 4), 256>>>();
    k_att3 <<<256, 256>>>(ef, adj, smk, h, out_w, out_b, gcn_w, gcn_b, ln_g, ln_b, out);
}

// round 16
// speedup vs baseline: 1.0894x; 1.0894x over previous
#include <cuda_runtime.h>

#define Bv 8
#define Nv 256
#define Dv 128
#define Ev 32
#define Hv 4
#define HDv 32
#define BN (Bv*Nv)

// ---------------- scratch (device globals; no allocation allowed) ----------------
__device__ float g_wke[Dv*Ev];
__device__ float g_wve[Dv*Ev];
__device__ float g_q  [BN*Dv];
__device__ float g_kh [BN*Dv];
__device__ float g_vh [BN*Dv];
__device__ float g_S0 [Bv*Hv*Nv*Nv];    // [b][h][n][m]
__device__ float g_hagg[BN*Dv];

// ---------------- K0: fused front: proj (blk<256) | gcn (256..511) | prep (512..543) ----
__global__ __launch_bounds__(384) void k_front(const float* __restrict__ hin,
                                               const float* __restrict__ adj,
                                               const float* __restrict__ wq,
                                               const float* __restrict__ wk,
                                               const float* __restrict__ wv,
                                               const float* __restrict__ bq,
                                               const float* __restrict__ bk,
                                               const float* __restrict__ bv,
                                               const float* __restrict__ edge_w,
                                               const float* __restrict__ edge_b) {
    int blk = blockIdx.x, t = threadIdx.x;
    if (blk < 256) {
        __shared__ float hs[9*Dv];
        int bn0 = blk << 3;
        for (int i = t; i < 9*Dv; i += 384)
            hs[i] = (i < 8*Dv) ? hin[(size_t)bn0*Dv + i] : edge_b[i - 8*Dv];
        __syncthreads();
        int mat = t >> 7, d = t & 127;
        const float* W = (mat == 0) ? wq : (mat == 1) ? wk : wv;
        float bias = (mat == 0) ? bq[d] : (mat == 1) ? bk[d] : bv[d];
        float acc[9];
        #pragma unroll
        for (int r = 0; r < 9; r++) acc[r] = 0.f;
        const float4* W4 = (const float4*)W;
        const float4* hs4 = (const float4*)hs;
        #pragma unroll 4
        for (int j4 = 0; j4 < 32; j4++) {
            float4 w = W4[d*32 + j4];
            #pragma unroll
            for (int r = 0; r < 9; r++) {
                float4 hv = hs4[r*32 + j4];
                acc[r] += w.x*hv.x + w.y*hv.y + w.z*hv.z + w.w*hv.w;
            }
        }
        float* dst = (mat == 0) ? g_q : (mat == 1) ? g_kh : g_vh;
        float cadd = (mat == 0) ? bias : (bias + acc[8]);
        #pragma unroll
        for (int r = 0; r < 8; r++)
            dst[(size_t)(bn0 + r)*Dv + d] = acc[r] + cadd;
    } else if (blk < 512) {
        __shared__ float adjs[8*Nv];
        __shared__ float part[3*8*Dv];
        __shared__ float degs[8];
        int g = blk - 256; int b = g >> 5; int n0 = (g & 31) << 3;
        for (int i = t; i < 8*Nv; i += 384) {
            int r = i >> 8, m = i & 255;
            adjs[i] = adj[((size_t)b*Nv + (n0+r))*Nv + m];
        }
        __syncthreads();
        if (t < 8) adjs[t*Nv + n0 + t] += 1.0f;
        __syncthreads();
        if (t < 128) {
            int r = t >> 4, lane = t & 15;
            float p = 0.f;
            #pragma unroll
            for (int k = 0; k < 16; k++) p += adjs[r*Nv + lane*16 + k];
            #pragma unroll
            for (int o = 8; o > 0; o >>= 1) p += __shfl_xor_sync(0xffffffffu, p, o, 16);
            if (lane == 0) degs[r] = p;
        }
        __syncthreads();
        int grp = t >> 7, d = t & 127;
        const int mlo = grp * 88;                       // 0, 88, 176
        const int mhi = (grp == 2) ? 256 : (mlo + 88);  // 88, 176, 256 (all /4)
        float acc[8];
        #pragma unroll
        for (int r = 0; r < 8; r++) acc[r] = 0.f;
        const float4* adjs4 = (const float4*)adjs;      // [r][m/4]
        const float* hb = hin + (size_t)b*Nv*Dv + d;
        for (int m4 = mlo; m4 < mhi; m4 += 4) {
            // front-batch 4 LDGs (coalesced across d)
            float hv0 = hb[(size_t)(m4+0)*Dv];
            float hv1 = hb[(size_t)(m4+1)*Dv];
            float hv2 = hb[(size_t)(m4+2)*Dv];
            float hv3 = hb[(size_t)(m4+3)*Dv];
            #pragma unroll
            for (int r = 0; r < 8; r++) {
                float4 ar = adjs4[r*(Nv/4) + (m4 >> 2)];   // LDS.128 broadcast
                acc[r] += ar.x*hv0 + ar.y*hv1 + ar.z*hv2 + ar.w*hv3;
            }
        }
        #pragma unroll
        for (int r = 0; r < 8; r++) part[grp*8*Dv + r*Dv + d] = acc[r];
        __syncthreads();
        if (t < 128) {
            #pragma unroll
            for (int r = 0; r < 8; r++) {
                float s = part[0*8*Dv + r*Dv + t] + part[1*8*Dv + r*Dv + t] + part[2*8*Dv + r*Dv + t];
                g_hagg[((size_t)b*Nv + n0 + r)*Dv + t] = s / degs[r];
            }
        }
    } else {
        if (t < 128) {
            int pb = blk - 512;
            int dl = t >> 5, e = t & 31;
            int d = pb * 4 + dl;
            float sk = 0.f, sv = 0.f;
            #pragma unroll 8
            for (int j = 0; j < Dv; j++) {
                float ew = edge_w[j*Ev + e];
                sk += wk[d*Dv + j] * ew;
                sv += wv[d*Dv + j] * ew;
            }
            g_wke[d*Ev + e] = sk;
            g_wve[d*Ev + e] = sv;
        }
    }
}

// ---------------- K1: S0 = Q_h K_h^T (32x64 tiles, grid 1024) ----------------
__global__ __launch_bounds__(256) void k_s0() {
    int bh = blockIdx.x; int b = bh >> 2, h = bh & 3;
    int n0 = blockIdx.y << 5, m0 = blockIdx.z << 6;
    __shared__ float Qt[32*33];
    __shared__ float Kt[64*33];
    int t = threadIdx.x;
    {
        int r = t >> 3, c4 = (t & 7) << 2;
        float4 w0 = *(const float4*)(g_kh + ((size_t)(b*Nv + m0 + r))*Dv + h*HDv + c4);
        float* q0 = &Kt[r*33 + c4];
        q0[0]=w0.x; q0[1]=w0.y; q0[2]=w0.z; q0[3]=w0.w;
        float4 w1 = *(const float4*)(g_kh + ((size_t)(b*Nv + m0 + 32 + r))*Dv + h*HDv + c4);
        float* q1 = &Kt[(32+r)*33 + c4];
        q1[0]=w1.x; q1[1]=w1.y; q1[2]=w1.z; q1[3]=w1.w;
        if (r < 32) {
            float4 v = *(const float4*)(g_q + ((size_t)(b*Nv + n0 + r))*Dv + h*HDv + c4);
            float* p = &Qt[r*33 + c4];
            p[0]=v.x; p[1]=v.y; p[2]=v.z; p[3]=v.w;
        }
    }
    __syncthreads();
    int tx = t & 15, ty = t >> 4;
    float acc[2][4];
    #pragma unroll
    for (int i = 0; i < 2; i++)
        #pragma unroll
        for (int j = 0; j < 4; j++) acc[i][j] = 0.f;
    #pragma unroll 4
    for (int e = 0; e < HDv; e++) {
        float qr[2], kr[4];
        qr[0] = Qt[(ty*2+0)*33 + e];
        qr[1] = Qt[(ty*2+1)*33 + e];
        #pragma unroll
        for (int j = 0; j < 4; j++) kr[j] = Kt[(tx*4+j)*33 + e];
        #pragma unroll
        for (int i = 0; i < 2; i++)
            #pragma unroll
            for (int j = 0; j < 4; j++) acc[i][j] += qr[i]*kr[j];
    }
    float* dst = g_S0 + (size_t)(b*Hv + h)*Nv*Nv;
    #pragma unroll
    for (int i = 0; i < 2; i++) {
        float* p = dst + (size_t)(n0 + ty*2 + i)*Nv + m0 + tx*4;
        *(float4*)p = make_float4(acc[i][0],acc[i][1],acc[i][2],acc[i][3]);
    }
}

// ------- K2: FUSED attention + out-proj + gcn-proj + LN (one CTA = 8 rows) --------
__global__ __launch_bounds__(256) void k_att3(const float* __restrict__ ef,
                                              const float* __restrict__ adj,
                                              const float* __restrict__ srcm,
                                              const float* __restrict__ hin,
                                              const float* __restrict__ out_w,
                                              const float* __restrict__ out_b,
                                              const float* __restrict__ gcn_w,
                                              const float* __restrict__ gcn_b,
                                              const float* __restrict__ ln_g,
                                              const float* __restrict__ ln_b,
                                              float* __restrict__ out) {
    int blk = blockIdx.x; int b = blk >> 5; int n0 = (blk & 31) << 3;
    __shared__ float sm[11520];            // 46080 B
    float* s_qrow = sm;                    // [8][128]  (later: aes; then hs)
    float* s_qks  = sm + 1024;             // [8][128]  (later: hag)
    float* s_efs  = sm + 2048;             // [8][32][33] pitch-33 (later: wvet; then yb/gb)
    float* s_exch = sm + 10496;            // [8][32] float4 (exp per head)
    float* s_os   = sm + 6144;             // [8][128] attention output (free zone during o2)

    int t = threadIdx.x;
    int n = t >> 5;                        // warp = n-row
    int x = t & 31;                        // lane
    int bn = b*Nv + n0 + n;

    *(float4*)&s_qrow[t*4] = *(const float4*)(g_q + ((size_t)(b*Nv + n0))*Dv + t*4);
    __syncwarp();
    #pragma unroll
    for (int h = 0; h < 4; h++) {
        float s = 0.f;
        #pragma unroll 8
        for (int j = 0; j < 32; j++)
            s += s_qrow[n*128 + h*32 + j] * g_wke[(h*32 + j)*Ev + x];
        s_qks[n*128 + h*32 + x] = s;
    }
    __syncwarp();

    const float SCALE = 0.17677669529663687f;   // 1/sqrt(32)
    float4 o1a = make_float4(0.f,0.f,0.f,0.f);
    float4 den4 = make_float4(0.f,0.f,0.f,0.f);
    float ae0=0.f, ae1=0.f, ae2=0.f, ae3=0.f;
    int ho = x >> 3;

    for (int mc = 0; mc < Nv; mc += 32) {
        int m = mc + x;
        {
            const float4* src = (const float4*)(ef + ((size_t)bn*Nv + mc)*Ev);
            float* dst = s_efs + n*1056;
            #pragma unroll
            for (int it = 0; it < 8; it++) {
                int idx = it*32 + x;
                int row = idx >> 3, e4 = idx & 7;
                float4 v = src[idx];
                float* p = &dst[row*33 + (e4 << 2)];
                p[0]=v.x; p[1]=v.y; p[2]=v.z; p[3]=v.w;
            }
        }
        float wmask = adj[(size_t)bn*Nv + m] * srcm[(size_t)bn*Nv + m];
        float s00 = g_S0[((size_t)(b*Hv+0)*Nv + (n0+n))*Nv + m];
        float s01 = g_S0[((size_t)(b*Hv+1)*Nv + (n0+n))*Nv + m];
        float s02 = g_S0[((size_t)(b*Hv+2)*Nv + (n0+n))*Nv + m];
        float s03 = g_S0[((size_t)(b*Hv+3)*Nv + (n0+n))*Nv + m];
        __syncwarp();
        float es0=0.f, es1=0.f, es2=0.f, es3=0.f;
        {
            const float* myrow = s_efs + n*1056 + x*33;
            #pragma unroll
            for (int e4 = 0; e4 < 8; e4++) {
                float f0 = myrow[e4*4+0], f1 = myrow[e4*4+1],
                      f2 = myrow[e4*4+2], f3 = myrow[e4*4+3];
                float4 q0 = *(const float4*)&s_qks[n*128 + 0*32 + e4*4];
                float4 q1 = *(const float4*)&s_qks[n*128 + 1*32 + e4*4];
                float4 q2 = *(const float4*)&s_qks[n*128 + 2*32 + e4*4];
                float4 q3 = *(const float4*)&s_qks[n*128 + 3*32 + e4*4];
                es0 += f0*q0.x + f1*q0.y + f2*q0.z + f3*q0.w;
                es1 += f0*q1.x + f1*q1.y + f2*q1.z + f3*q1.w;
                es2 += f0*q2.x + f1*q2.y + f2*q2.z + f3*q2.w;
                es3 += f0*q3.x + f1*q3.y + f2*q3.z + f3*q3.w;
            }
        }
        float4 exv;
        if (wmask == 0.0f) {
            exv = make_float4(0.f,0.f,0.f,0.f);
        } else {
            exv.x = __expf((s00+es0)*SCALE);
            exv.y = __expf((s01+es1)*SCALE);
            exv.z = __expf((s02+es2)*SCALE);
            exv.w = __expf((s03+es3)*SCALE);
        }
        *(float4*)&s_exch[t*4] = exv;
        {
            float4 cs = exv;
            #pragma unroll
            for (int o = 16; o > 0; o >>= 1) {
                cs.x += __shfl_xor_sync(0xffffffffu, cs.x, o);
                cs.y += __shfl_xor_sync(0xffffffffu, cs.y, o);
                cs.z += __shfl_xor_sync(0xffffffffu, cs.z, o);
                cs.w += __shfl_xor_sync(0xffffffffu, cs.w, o);
            }
            den4.x += cs.x; den4.y += cs.y; den4.z += cs.z; den4.w += cs.w;
        }
        __syncwarp();

        const float* vbase = g_vh + ((size_t)(b*Nv + mc))*Dv;
        #pragma unroll 4
        for (int mm = 0; mm < 32; mm++) {
            float exm = s_exch[(n*32+mm)*4 + ho];
            float4 vv = *(const float4*)(vbase + (size_t)mm*Dv + x*4);
            o1a.x += exm*vv.x; o1a.y += exm*vv.y; o1a.z += exm*vv.z; o1a.w += exm*vv.w;
        }
        {
            const float* wef = s_efs + n*1056;
            #pragma unroll 4
            for (int mm = 0; mm < 32; mm++) {
                float4 e4v = *(const float4*)&s_exch[(n*32+mm)*4];
                float fv = wef[mm*33 + x];
                ae0 += e4v.x*fv; ae1 += e4v.y*fv; ae2 += e4v.z*fv; ae3 += e4v.w*fv;
            }
        }
        __syncwarp();
    }

    // normalize ae -> aes (reuse s_qrow)
    {
        float* aes = s_qrow;
        aes[(n*4+0)*32 + x] = ae0 / den4.x;
        aes[(n*4+1)*32 + x] = ae1 / den4.y;
        aes[(n*4+2)*32 + x] = ae2 / den4.z;
        aes[(n*4+3)*32 + x] = ae3 / den4.w;
    }
    __syncthreads();
    // stage wve^T (32e x 128d) into s_efs (first 16 KB)
    #pragma unroll
    for (int i = 0; i < 16; i++) {
        int idx = i*256 + t;
        int e = idx >> 7, d = idx & 127;
        s_efs[e*128 + d] = g_wve[d*Ev + e];
    }
    __syncthreads();
    // o2 + write attention output into smem os
    {
        float den1 = (ho == 0) ? den4.x : (ho == 1) ? den4.y : (ho == 2) ? den4.z : den4.w;
        float inv = 1.0f / den1;
        float4 res = make_float4(o1a.x*inv, o1a.y*inv, o1a.z*inv, o1a.w*inv);
        const float* aes = s_qrow + (n*4 + ho)*32;
        #pragma unroll 8
        for (int e = 0; e < 32; e++) {
            float a = aes[e];
            float4 wv = *(const float4*)&s_efs[e*128 + x*4];
            res.x += a*wv.x; res.y += a*wv.y; res.z += a*wv.z; res.w += a*wv.w;
        }
        *(float4*)&s_os[n*128 + x*4] = res;
    }
    __syncthreads();   // os complete; aes/wvet now dead -> overlay tail buffers

    // ---- fused former k_final: out-proj + gcn-proj + LN for these 8 rows ----
    float* s_hs  = sm;            // [8][128]
    float* s_hag = sm + 1024;     // [8][128]
    float* s_yb  = sm + 2048;     // [8][128]
    float* s_gb  = sm + 3072;     // [8][128]
    {
        size_t gi = (size_t)(b*Nv + n0)*Dv;
        *(float4*)&s_hs [t*4] = *(const float4*)(hin   + gi + t*4);
        *(float4*)&s_hag[t*4] = *(const float4*)(g_hagg + gi + t*4);
    }
    __syncthreads();
    {
        int grp = t >> 7, d = t & 127;
        const float4* W4 = (const float4*)(grp ? gcn_w : out_w);
        const float4* X4 = (const float4*)(grp ? s_hag : s_os);
        float bias = grp ? gcn_b[d] : out_b[d];
        float* Y = grp ? s_gb : s_yb;
        float acc[8];
        #pragma unroll
        for (int r = 0; r < 8; r++) acc[r] = bias;
        #pragma unroll 4
        for (int j4 = 0; j4 < 32; j4++) {
            float4 w = W4[d*32 + j4];
            #pragma unroll
            for (int r = 0; r < 8; r++) {
                float4 hv = X4[r*32 + j4];
                acc[r] += w.x*hv.x + w.y*hv.y + w.z*hv.z + w.w*hv.w;
            }
        }
        #pragma unroll
        for (int r = 0; r < 8; r++) Y[r*Dv + d] = acc[r];
    }
    __syncthreads();
    {
        float4 a  = *(const float4*)&s_hs[n*128 + x*4];
        float4 yv = *(const float4*)&s_yb[n*128 + x*4];
        float x0 = a.x + yv.x, x1 = a.y + yv.y, x2 = a.z + yv.z, x3 = a.w + yv.w;
        float s = x0 + x1 + x2 + x3;
        #pragma unroll
        for (int o = 16; o > 0; o >>= 1) s += __shfl_xor_sync(0xffffffffu, s, o);
        float mu = s * (1.0f/128.0f);
        float c0 = x0-mu, c1 = x1-mu, c2 = x2-mu, c3 = x3-mu;
        float vv = c0*c0 + c1*c1 + c2*c2 + c3*c3;
        #pragma unroll
        for (int o = 16; o > 0; o >>= 1) vv += __shfl_xor_sync(0xffffffffu, vv, o);
        float rs = rsqrtf(vv * (1.0f/128.0f) + 1e-5f);
        float4 g  = ((const float4*)ln_g)[x];
        float4 lb = ((const float4*)ln_b)[x];
        float4 gg = *(const float4*)&s_gb[n*128 + x*4];
        float4 res;
        res.x = gg.x + g.x*c0*rs + lb.x;
        res.y = gg.y + g.y*c1*rs + lb.y;
        res.z = gg.z + g.z*c2*rs + lb.z;
        res.w = gg.w + g.w*c3*rs + lb.w;
        *(float4*)(out + (size_t)bn*Dv + x*4) = res;
    }
}

extern "C" void kernel_launch(void* const* d_in, const int* in_sizes, int n_in,
                              void* d_out, int out_size) {
    const float* h     = (const float*)d_in[0];
    const float* adj   = (const float*)d_in[1];
    const float* ef    = (const float*)d_in[2];
    const float* smk   = (const float*)d_in[3];
    const float* gcn_w = (const float*)d_in[4];
    const float* gcn_b = (const float*)d_in[5];
    const float* edge_w= (const float*)d_in[6];
    const float* edge_b= (const float*)d_in[7];
    const float* wq    = (const float*)d_in[8];
    const float* wk    = (const float*)d_in[9];
    const float* wv    = (const float*)d_in[10];
    const float* bq    = (const float*)d_in[11];
    const float* bk    = (const float*)d_in[12];
    const float* bv    = (const float*)d_in[13];
    const float* out_w = (const float*)d_in[14];
    const float* out_b = (const float*)d_in[15];
    const float* ln_g  = (const float*)d_in[16];
    const float* ln_b  = (const float*)d_in[17];
    float* out = (float*)d_out;

    k_front<<<544, 384>>>(h, adj, wq, wk, wv, bq, bk, bv, edge_w, edge_b);
    k_s0   <<<dim3(Bv*Hv, 8, 4), 256>>>();
    k_att3 <<<256, 256>>>(ef, adj, smk, h, out_w, out_b, gcn_w, gcn_b, ln_g, ln_b, out);
}